// round 1
// baseline (speedup 1.0000x reference)
#include <cuda_runtime.h>
#include <math.h>

#define N_NODES 100000
#define E_EDGES 3200000
#define S_SAMP  1000000
#define F_IN    512
#define FULLM   0xffffffffu

// ---------------- device scratch (static: no allocations allowed) ----------------
__device__ int   g_cnt[N_NODES];          // in-degree counts
__device__ int   g_cur[N_NODES];          // placement cursors
__device__ int   g_off[N_NODES];          // CSR exclusive offsets
__device__ int   g_bsum[128];
__device__ int   g_boff[128];
__device__ int   g_tsrc[E_EDGES];
__device__ int   g_tdst[E_EDGES];
__device__ int   g_esrc[E_EDGES];         // src sorted by dst (CSR payload)
__device__ float g_dinv[N_NODES];
__device__ __align__(16) float g_y1[N_NODES * 8];
__device__ __align__(16) float g_y2[N_NODES * 16];
__device__ __align__(16) float g_y3[N_NODES * 32];
__device__ __align__(16) float g_h3[N_NODES * 32];
__device__ int g_flags[2];                // [0]: edge_index is int32, [1]: samples is int32

// ---------------- init ----------------
__global__ void k_zero() {
    int i = blockIdx.x * blockDim.x + threadIdx.x;
    if (i < N_NODES) { g_cnt[i] = 0; g_cur[i] = 0; }
    if (i < 2) g_flags[i] = 0;
}

// Detect int64 vs int32 index buffers: for little-endian int64 with values < 2^31,
// every odd 32-bit word is 0. For int32 data, odd words are random node indices.
__global__ void k_detect(const int* __restrict__ ei, const int* __restrict__ sm) {
    int t = threadIdx.x;
    int e_nz = 0, s_nz = 0;
    for (int k = t; k < 1024; k += 256) {
        if (ei[2 * k + 1] != 0) e_nz = 1;
        if (sm[2 * k + 1] != 0) s_nz = 1;
    }
    if (e_nz) atomicOr(&g_flags[0], 1);
    if (s_nz) atomicOr(&g_flags[1], 1);
}

// ---------------- edge preprocessing: count + stash as int32 ----------------
__global__ void k_count(const void* __restrict__ eip) {
    int e = blockIdx.x * blockDim.x + threadIdx.x;
    if (e >= E_EDGES) return;
    int s, d;
    if (g_flags[0]) {
        const int* p = (const int*)eip;
        s = p[e]; d = p[E_EDGES + e];
    } else {
        const long long* p = (const long long*)eip;
        s = (int)p[e]; d = (int)p[(size_t)E_EDGES + e];
    }
    g_tsrc[e] = s; g_tdst[e] = d;
    atomicAdd(&g_cnt[d], 1);
}

// ---------------- 3-kernel exclusive scan of g_cnt -> g_off ----------------
__global__ void k_scanA() {
    __shared__ int sh[1024];
    int t = threadIdx.x;
    int i = blockIdx.x * 1024 + t;
    int v = (i < N_NODES) ? g_cnt[i] : 0;
    sh[t] = v; __syncthreads();
    for (int off = 1; off < 1024; off <<= 1) {
        int u = (t >= off) ? sh[t - off] : 0;
        __syncthreads();
        sh[t] += u;
        __syncthreads();
    }
    if (i < N_NODES) g_off[i] = sh[t];          // inclusive for now
    if (t == 1023) g_bsum[blockIdx.x] = sh[1023];
}

__global__ void k_scanB(int nb) {
    __shared__ int sh[128];
    int t = threadIdx.x;
    int v = (t < nb) ? g_bsum[t] : 0;
    sh[t] = v; __syncthreads();
    for (int off = 1; off < 128; off <<= 1) {
        int u = (t >= off) ? sh[t - off] : 0;
        __syncthreads();
        sh[t] += u;
        __syncthreads();
    }
    g_boff[t] = sh[t] - v;                       // exclusive block offsets
}

__global__ void k_scanC() {
    int i = blockIdx.x * blockDim.x + threadIdx.x;
    if (i >= N_NODES) return;
    g_off[i] = g_off[i] - g_cnt[i] + g_boff[i >> 10];   // inclusive -> exclusive + block base
}

// ---------------- counting-sort placement (src sorted by dst) ----------------
__global__ void k_place() {
    int e = blockIdx.x * blockDim.x + threadIdx.x;
    if (e >= E_EDGES) return;
    int d = g_tdst[e];
    int pos = g_off[d] + atomicAdd(&g_cur[d], 1);
    g_esrc[pos] = g_tsrc[e];
}

__global__ void k_dinv() {
    int i = blockIdx.x * blockDim.x + threadIdx.x;
    if (i >= N_NODES) return;
    g_dinv[i] = rsqrtf((float)g_cnt[i] + 1.0f);
}

// ---------------- y1 = dinv * (x @ W1) : 100000x512 @ 512x8 ----------------
// Thread-per-node with shared-staged x chunks (coalesced gmem) and broadcast W reads.
__global__ void __launch_bounds__(128) k_mm1(const float* __restrict__ x,
                                             const float* __restrict__ W1) {
    __shared__ float4 sW[1024];       // W1: 512x8 floats = 1024 float4
    __shared__ float4 sx[128 * 9];    // 128 nodes x 8 float4 (+pad) per K-chunk of 32
    int t = threadIdx.x;
    const float4* W14 = (const float4*)W1;
    for (int i = t; i < 1024; i += 128) sW[i] = W14[i];

    int n = blockIdx.x * 128 + t;
    const float4* x4 = (const float4*)x;
    float4 a0 = {0, 0, 0, 0}, a1 = {0, 0, 0, 0};

    for (int c = 0; c < 16; c++) {
        __syncthreads();
        #pragma unroll
        for (int r = 0; r < 8; r++) {
            int idx = t + 128 * r;            // 0..1023
            int nn = idx >> 3, k4 = idx & 7;
            int gn = blockIdx.x * 128 + nn;
            if (gn > N_NODES - 1) gn = N_NODES - 1;
            sx[nn * 9 + k4] = x4[(size_t)gn * 128 + c * 8 + k4];
        }
        __syncthreads();
        #pragma unroll
        for (int k4 = 0; k4 < 8; k4++) {
            float4 xv = sx[t * 9 + k4];
            int kb = c * 32 + k4 * 4;
            #define FMA8(xs, kk) { float4 wa = sW[(kk)*2]; float4 wb = sW[(kk)*2+1]; \
                a0.x += (xs)*wa.x; a0.y += (xs)*wa.y; a0.z += (xs)*wa.z; a0.w += (xs)*wa.w; \
                a1.x += (xs)*wb.x; a1.y += (xs)*wb.y; a1.z += (xs)*wb.z; a1.w += (xs)*wb.w; }
            FMA8(xv.x, kb + 0);
            FMA8(xv.y, kb + 1);
            FMA8(xv.z, kb + 2);
            FMA8(xv.w, kb + 3);
            #undef FMA8
        }
    }
    if (n < N_NODES) {
        float di = g_dinv[n];
        a0.x *= di; a0.y *= di; a0.z *= di; a0.w *= di;
        a1.x *= di; a1.y *= di; a1.z *= di; a1.w *= di;
        float4* y14 = (float4*)g_y1;
        y14[n * 2 + 0] = a0;
        y14[n * 2 + 1] = a1;
    }
}

// ---------------- Layer 1: agg(y1) -> h1 = relu -> y2 = dinv*(h1@W2) ----------------
// Warp per destination node. F_in = 8, F_out = 16.
__global__ void __launch_bounds__(256) k_layer1(const float* __restrict__ b1,
                                                const float* __restrict__ W2) {
    __shared__ float sW2[128];   // 8x16
    int t = threadIdx.x;
    if (t < 128) sW2[t] = W2[t];
    __syncthreads();
    int warp = t >> 5, lane = t & 31;
    int n = blockIdx.x * 8 + warp;
    if (n >= N_NODES) return;
    int e0 = g_off[n], cnt = g_cnt[n];
    int f = lane & 7;
    float acc = 0.f;
    for (int e = (lane >> 3); e < cnt; e += 4) {
        int s = g_esrc[e0 + e];
        acc += __ldg(&g_y1[s * 8 + f]);
    }
    acc += __shfl_down_sync(FULLM, acc, 16);
    acc += __shfl_down_sync(FULLM, acc, 8);
    float di = g_dinv[n];
    float h = 0.f;
    if (lane < 8) h = fmaxf(di * (acc + g_y1[n * 8 + lane]) + b1[lane], 0.f);
    float out = 0.f;
    int j = lane & 15;
    #pragma unroll
    for (int k = 0; k < 8; k++) {
        float hk = __shfl_sync(FULLM, h, k);
        out += hk * sW2[k * 16 + j];
    }
    if (lane < 16) g_y2[n * 16 + lane] = di * out;
}

// ---------------- Layer 2: agg(y2) -> h2 = relu -> y3 = dinv*(h2@W3) ----------------
// F_in = 16, F_out = 32.
__global__ void __launch_bounds__(256) k_layer2(const float* __restrict__ b2,
                                                const float* __restrict__ W3) {
    __shared__ float sW3[512];   // 16x32
    int t = threadIdx.x;
    for (int i = t; i < 512; i += 256) sW3[i] = W3[i];
    __syncthreads();
    int warp = t >> 5, lane = t & 31;
    int n = blockIdx.x * 8 + warp;
    if (n >= N_NODES) return;
    int e0 = g_off[n], cnt = g_cnt[n];
    int f = lane & 15;
    float acc = 0.f;
    for (int e = (lane >> 4); e < cnt; e += 2) {
        int s = g_esrc[e0 + e];
        acc += __ldg(&g_y2[s * 16 + f]);
    }
    acc += __shfl_down_sync(FULLM, acc, 16);
    float di = g_dinv[n];
    float h = 0.f;
    if (lane < 16) h = fmaxf(di * (acc + g_y2[n * 16 + lane]) + b2[lane], 0.f);
    float out = 0.f;
    #pragma unroll
    for (int k = 0; k < 16; k++) {
        float hk = __shfl_sync(FULLM, h, k);
        out += hk * sW3[k * 32 + lane];
    }
    g_y3[n * 32 + lane] = di * out;
}

// ---------------- Layer 3: agg(y3) -> h3 (no relu, no matmul) ----------------
__global__ void __launch_bounds__(256) k_layer3(const float* __restrict__ b3) {
    int t = threadIdx.x;
    int warp = t >> 5, lane = t & 31;
    int n = blockIdx.x * 8 + warp;
    if (n >= N_NODES) return;
    int e0 = g_off[n], cnt = g_cnt[n];
    float acc = 0.f;
    for (int e = 0; e < cnt; e++) {
        int s = g_esrc[e0 + e];
        acc += __ldg(&g_y3[s * 32 + lane]);
    }
    float di = g_dinv[n];
    g_h3[n * 32 + lane] = di * (acc + g_y3[n * 32 + lane]) + b3[lane];
}

// ---------------- Final: per-sample concat-dot + sigmoid (4 lanes / sample) ----------------
__global__ void __launch_bounds__(256) k_final(const void* __restrict__ smp,
                                               const float* __restrict__ Wfc,
                                               const float* __restrict__ bfc,
                                               float* __restrict__ out) {
    __shared__ float4 sW[16];
    __shared__ float sb;
    int t = threadIdx.x;
    if (t < 16) sW[t] = ((const float4*)Wfc)[t];
    if (t == 0) sb = bfc[0];
    __syncthreads();
    int gid = blockIdx.x * 256 + t;
    int s = gid >> 2, q = gid & 3;
    if (s >= S_SAMP) return;
    long long i, j;
    if (g_flags[1]) {
        const int* p = (const int*)smp;
        i = p[2 * s]; j = p[2 * s + 1];
    } else {
        const long long* p = (const long long*)smp;
        i = p[2 * (size_t)s]; j = p[2 * (size_t)s + 1];
    }
    const float4* h4 = (const float4*)g_h3;
    float acc = 0.f;
    float4 v, w;
    v = __ldg(&h4[(size_t)i * 8 + q]);     w = sW[q];
    acc += v.x * w.x + v.y * w.y + v.z * w.z + v.w * w.w;
    v = __ldg(&h4[(size_t)i * 8 + q + 4]); w = sW[q + 4];
    acc += v.x * w.x + v.y * w.y + v.z * w.z + v.w * w.w;
    v = __ldg(&h4[(size_t)j * 8 + q]);     w = sW[8 + q];
    acc += v.x * w.x + v.y * w.y + v.z * w.z + v.w * w.w;
    v = __ldg(&h4[(size_t)j * 8 + q + 4]); w = sW[12 + q];
    acc += v.x * w.x + v.y * w.y + v.z * w.z + v.w * w.w;
    acc += __shfl_xor_sync(FULLM, acc, 1);
    acc += __shfl_xor_sync(FULLM, acc, 2);
    if (q == 0) out[s] = 1.f / (1.f + __expf(-(acc + sb)));
}

// ---------------- launch ----------------
extern "C" void kernel_launch(void* const* d_in, const int* in_sizes, int n_in,
                              void* d_out, int out_size) {
    const float* x   = (const float*)d_in[0];
    const void*  ei  = d_in[1];
    const void*  smp = d_in[2];
    const float* W1  = (const float*)d_in[3];
    const float* b1  = (const float*)d_in[4];
    const float* W2  = (const float*)d_in[5];
    const float* b2  = (const float*)d_in[6];
    const float* W3  = (const float*)d_in[7];
    const float* b3  = (const float*)d_in[8];
    const float* Wfc = (const float*)d_in[9];
    const float* bfc = (const float*)d_in[10];
    float* out = (float*)d_out;

    const int nb_scan = (N_NODES + 1023) / 1024;   // 98

    k_zero<<<(N_NODES + 255) / 256, 256>>>();
    k_detect<<<1, 256>>>((const int*)ei, (const int*)smp);
    k_count<<<(E_EDGES + 255) / 256, 256>>>(ei);
    k_scanA<<<nb_scan, 1024>>>();
    k_scanB<<<1, 128>>>(nb_scan);
    k_scanC<<<(N_NODES + 255) / 256, 256>>>();
    k_place<<<(E_EDGES + 255) / 256, 256>>>();
    k_dinv<<<(N_NODES + 255) / 256, 256>>>();
    k_mm1<<<(N_NODES + 127) / 128, 128>>>(x, W1);
    k_layer1<<<(N_NODES + 7) / 8, 256>>>(b1, W2);
    k_layer2<<<(N_NODES + 7) / 8, 256>>>(b2, W3);
    k_layer3<<<(N_NODES + 7) / 8, 256>>>(b3);
    k_final<<<(4 * S_SAMP + 255) / 256, 256>>>(smp, Wfc, bfc, out);
}

// round 2
// speedup vs baseline: 1.1574x; 1.1574x over previous
#include <cuda_runtime.h>
#include <math.h>

#define N_NODES 100000
#define E_EDGES 3200000
#define S_SAMP  1000000
#define FULLM   0xffffffffu

// ---------------- device scratch (static: no allocations allowed) ----------------
__device__ __align__(16) int   g_cnt[N_NODES];
__device__ __align__(16) int   g_off[N_NODES];
__device__ int   g_bsum[128];
__device__ int   g_boff[128];
__device__ int   g_tsrc[E_EDGES];
__device__ int   g_tdst[E_EDGES];
__device__ int   g_esrc[E_EDGES];         // src sorted by dst (CSR payload)
__device__ float g_dinv[N_NODES];
__device__ __align__(16) float g_y1[N_NODES * 8];
__device__ __align__(16) float g_y2[N_NODES * 16];
__device__ __align__(8)  float2 g_z[N_NODES];    // (y3 . Wa, y3 . Wb)
__device__ float g_sa[N_NODES];
__device__ float g_sb[N_NODES];
__device__ float2 g_cab;                  // (b3 . Wa, b3 . Wb)
__device__ int g_flags[2];                // [0]: edge_index is int32, [1]: samples is int32

// ---------------- init: zero counts + dtype detection ----------------
__global__ void k_init(const int* __restrict__ ei, const int* __restrict__ sm) {
    int i = blockIdx.x * blockDim.x + threadIdx.x;
    if (i < N_NODES) g_cnt[i] = 0;
    if (blockIdx.x == 0) {
        if (threadIdx.x == 0) { g_flags[0] = 0; g_flags[1] = 0; }
        __syncthreads();
        int e_nz = 0, s_nz = 0;
        for (int k = threadIdx.x; k < 1024; k += 256) {
            if (ei[2 * k + 1] != 0) e_nz = 1;
            if (sm[2 * k + 1] != 0) s_nz = 1;
        }
        if (e_nz) atomicOr(&g_flags[0], 1);
        if (s_nz) atomicOr(&g_flags[1], 1);
    }
}

// ---------------- edge preprocessing: count + stash as int32 ----------------
__global__ void k_count(const void* __restrict__ eip) {
    int e = blockIdx.x * blockDim.x + threadIdx.x;
    if (e >= E_EDGES) return;
    int s, d;
    if (g_flags[0]) {
        const int* p = (const int*)eip;
        s = p[e]; d = p[E_EDGES + e];
    } else {
        const long long* p = (const long long*)eip;
        s = (int)p[e]; d = (int)p[(size_t)E_EDGES + e];
    }
    g_tsrc[e] = s; g_tdst[e] = d;
    atomicAdd(&g_cnt[d], 1);
}

// ---------------- scan: 1024 elems / 256-thread block, shuffle based ----------------
__global__ void __launch_bounds__(256) k_scanA() {
    __shared__ int ws[8];
    __shared__ int wtot;
    int t = threadIdx.x, lane = t & 31, warp = t >> 5;
    int base = blockIdx.x * 1024 + t * 4;
    int4 v = make_int4(0, 0, 0, 0);
    if (base + 3 < N_NODES) v = *(const int4*)&g_cnt[base];
    else {
        if (base + 0 < N_NODES) v.x = g_cnt[base + 0];
        if (base + 1 < N_NODES) v.y = g_cnt[base + 1];
        if (base + 2 < N_NODES) v.z = g_cnt[base + 2];
    }
    int tsum = v.x + v.y + v.z + v.w;
    int inc = tsum;
    #pragma unroll
    for (int o = 1; o < 32; o <<= 1) {
        int u = __shfl_up_sync(FULLM, inc, o);
        if (lane >= o) inc += u;
    }
    if (lane == 31) ws[warp] = inc;
    __syncthreads();
    if (warp == 0) {
        int w = (lane < 8) ? ws[lane] : 0;
        int wi = w;
        #pragma unroll
        for (int o = 1; o < 8; o <<= 1) {
            int u = __shfl_up_sync(FULLM, wi, o);
            if (lane >= o) wi += u;
        }
        if (lane < 8) ws[lane] = wi - w;      // exclusive warp base
        if (lane == 7) wtot = wi;             // block total
    }
    __syncthreads();
    int b = ws[warp] + inc - tsum;            // exclusive thread base
    int4 o;
    o.x = b + v.x; o.y = o.x + v.y; o.z = o.y + v.z; o.w = o.z + v.w;
    if (base + 3 < N_NODES) *(int4*)&g_off[base] = o;   // inclusive (fixed in scanC)
    else {
        if (base + 0 < N_NODES) g_off[base + 0] = o.x;
        if (base + 1 < N_NODES) g_off[base + 1] = o.y;
        if (base + 2 < N_NODES) g_off[base + 2] = o.z;
    }
    if (t == 0) g_bsum[blockIdx.x] = wtot;
}

__global__ void k_scanB(int nb) {
    __shared__ int sh[128];
    int t = threadIdx.x;
    int v = (t < nb) ? g_bsum[t] : 0;
    sh[t] = v; __syncthreads();
    for (int off = 1; off < 128; off <<= 1) {
        int u = (t >= off) ? sh[t - off] : 0;
        __syncthreads();
        sh[t] += u;
        __syncthreads();
    }
    g_boff[t] = sh[t] - v;                    // exclusive block offsets
}

// inclusive -> global exclusive; also dinv and head constants
__global__ void k_scanC(const float* __restrict__ b3, const float* __restrict__ Wfc) {
    int i = blockIdx.x * blockDim.x + threadIdx.x;
    if (i < N_NODES) {
        int c = g_cnt[i];
        g_off[i] = g_off[i] - c + g_boff[i >> 10];
        g_dinv[i] = rsqrtf((float)c + 1.0f);
    }
    if (i == 0) {
        float ca = 0.f, cb = 0.f;
        #pragma unroll
        for (int f = 0; f < 32; f++) { ca += b3[f] * Wfc[f]; cb += b3[f] * Wfc[32 + f]; }
        g_cab = make_float2(ca, cb);
    }
}

// ---------------- counting-sort placement (atomic cursor on g_off) ----------------
// After this kernel g_off[n] == end of bucket n; layers use e0 = g_off[n] - g_cnt[n].
__global__ void k_place() {
    int e = blockIdx.x * blockDim.x + threadIdx.x;
    if (e >= E_EDGES) return;
    int d = g_tdst[e];
    int pos = atomicAdd(&g_off[d], 1);
    g_esrc[pos] = g_tsrc[e];
}

// ---------------- y1 = dinv * (x @ W1) : 100000x512 @ 512x8 ----------------
__global__ void __launch_bounds__(128) k_mm1(const float* __restrict__ x,
                                             const float* __restrict__ W1) {
    __shared__ float4 sW[1024];       // W1: 512x8 floats = 1024 float4
    __shared__ float4 sx[128 * 9];    // 128 nodes x 8 float4 (+pad) per K-chunk of 32
    int t = threadIdx.x;
    const float4* W14 = (const float4*)W1;
    for (int i = t; i < 1024; i += 128) sW[i] = W14[i];

    int n = blockIdx.x * 128 + t;
    const float4* x4 = (const float4*)x;
    float4 a0 = {0, 0, 0, 0}, a1 = {0, 0, 0, 0};

    for (int c = 0; c < 16; c++) {
        __syncthreads();
        #pragma unroll
        for (int r = 0; r < 8; r++) {
            int idx = t + 128 * r;            // 0..1023
            int nn = idx >> 3, k4 = idx & 7;
            int gn = blockIdx.x * 128 + nn;
            if (gn > N_NODES - 1) gn = N_NODES - 1;
            sx[nn * 9 + k4] = x4[(size_t)gn * 128 + c * 8 + k4];
        }
        __syncthreads();
        #pragma unroll
        for (int k4 = 0; k4 < 8; k4++) {
            float4 xv = sx[t * 9 + k4];
            int kb = c * 32 + k4 * 4;
            #define FMA8(xs, kk) { float4 wa = sW[(kk)*2]; float4 wb = sW[(kk)*2+1]; \
                a0.x += (xs)*wa.x; a0.y += (xs)*wa.y; a0.z += (xs)*wa.z; a0.w += (xs)*wa.w; \
                a1.x += (xs)*wb.x; a1.y += (xs)*wb.y; a1.z += (xs)*wb.z; a1.w += (xs)*wb.w; }
            FMA8(xv.x, kb + 0);
            FMA8(xv.y, kb + 1);
            FMA8(xv.z, kb + 2);
            FMA8(xv.w, kb + 3);
            #undef FMA8
        }
    }
    if (n < N_NODES) {
        float di = g_dinv[n];
        a0.x *= di; a0.y *= di; a0.z *= di; a0.w *= di;
        a1.x *= di; a1.y *= di; a1.z *= di; a1.w *= di;
        float4* y14 = (float4*)g_y1;
        y14[n * 2 + 0] = a0;
        y14[n * 2 + 1] = a1;
    }
}

// ---------------- Layer 1: agg(y1) -> relu -> y2 = dinv*(h1@W2) ----------------
__global__ void __launch_bounds__(256) k_layer1(const float* __restrict__ b1,
                                                const float* __restrict__ W2) {
    __shared__ float sW2[128];   // 8x16
    int t = threadIdx.x;
    if (t < 128) sW2[t] = W2[t];
    __syncthreads();
    int warp = t >> 5, lane = t & 31;
    int n = blockIdx.x * 8 + warp;
    if (n >= N_NODES) return;
    int end = g_off[n], cnt = g_cnt[n], e0 = end - cnt;
    int f = lane & 7;
    float acc = 0.f;
    for (int e = (lane >> 3); e < cnt; e += 4) {
        int s = g_esrc[e0 + e];
        acc += __ldg(&g_y1[s * 8 + f]);
    }
    acc += __shfl_down_sync(FULLM, acc, 16);
    acc += __shfl_down_sync(FULLM, acc, 8);
    float di = g_dinv[n];
    float h = 0.f;
    if (lane < 8) h = fmaxf(di * (acc + g_y1[n * 8 + lane]) + b1[lane], 0.f);
    float out = 0.f;
    int j = lane & 15;
    #pragma unroll
    for (int k = 0; k < 8; k++) {
        float hk = __shfl_sync(FULLM, h, k);
        out += hk * sW2[k * 16 + j];
    }
    if (lane < 16) g_y2[n * 16 + lane] = di * out;
}

// ---------------- Layer 2: agg(y2) -> relu -> y3 = dinv*(h2@W3), then collapse to z ----------------
__global__ void __launch_bounds__(256) k_layer2(const float* __restrict__ b2,
                                                const float* __restrict__ W3,
                                                const float* __restrict__ Wfc) {
    __shared__ float sW3[512];   // 16x32
    __shared__ float sWfc[64];
    int t = threadIdx.x;
    for (int i = t; i < 512; i += 256) sW3[i] = W3[i];
    if (t < 64) sWfc[t] = Wfc[t];
    __syncthreads();
    int warp = t >> 5, lane = t & 31;
    int n = blockIdx.x * 8 + warp;
    if (n >= N_NODES) return;
    int end = g_off[n], cnt = g_cnt[n], e0 = end - cnt;
    int f = lane & 15;
    float acc = 0.f;
    for (int e = (lane >> 4); e < cnt; e += 2) {
        int s = g_esrc[e0 + e];
        acc += __ldg(&g_y2[s * 16 + f]);
    }
    acc += __shfl_down_sync(FULLM, acc, 16);
    float di = g_dinv[n];
    float h = 0.f;
    if (lane < 16) h = fmaxf(di * (acc + g_y2[n * 16 + lane]) + b2[lane], 0.f);
    float out = 0.f;
    #pragma unroll
    for (int k = 0; k < 16; k++) {
        float hk = __shfl_sync(FULLM, h, k);
        out += hk * sW3[k * 32 + lane];
    }
    float y3v = di * out;                       // y3[n][lane]
    float za = y3v * sWfc[lane];
    float zb = y3v * sWfc[32 + lane];
    #pragma unroll
    for (int o = 16; o; o >>= 1) {
        za += __shfl_xor_sync(FULLM, za, o);
        zb += __shfl_xor_sync(FULLM, zb, o);
    }
    if (lane == 0) g_z[n] = make_float2(za, zb);
}

// ---------------- Layer 3 (scalarized): sa/sb = dinv*(sum z[src] + z[n]) + cab ----------------
__global__ void __launch_bounds__(256) k_layer3() {
    int t = threadIdx.x;
    int warp = t >> 5, lane = t & 31;
    int n = blockIdx.x * 8 + warp;
    if (n >= N_NODES) return;
    int end = g_off[n], cnt = g_cnt[n], e0 = end - cnt;
    float ax = 0.f, ay = 0.f;
    for (int e = lane; e < cnt; e += 32) {
        int s = g_esrc[e0 + e];
        float2 z = __ldg(&g_z[s]);
        ax += z.x; ay += z.y;
    }
    #pragma unroll
    for (int o = 16; o; o >>= 1) {
        ax += __shfl_xor_sync(FULLM, ax, o);
        ay += __shfl_xor_sync(FULLM, ay, o);
    }
    if (lane == 0) {
        float di = g_dinv[n];
        float2 zn = g_z[n];
        g_sa[n] = di * (ax + zn.x) + g_cab.x;
        g_sb[n] = di * (ay + zn.y) + g_cab.y;
    }
}

// ---------------- Final: out[s] = sigmoid(sa[i] + sb[j] + bfc) ----------------
__global__ void __launch_bounds__(256) k_final(const void* __restrict__ smp,
                                               const float* __restrict__ bfc,
                                               float* __restrict__ out) {
    int s = blockIdx.x * 256 + threadIdx.x;
    if (s >= S_SAMP) return;
    long long i, j;
    if (g_flags[1]) {
        const int* p = (const int*)smp;
        i = p[2 * s]; j = p[2 * s + 1];
    } else {
        const long long* p = (const long long*)smp;
        i = p[2 * (size_t)s]; j = p[2 * (size_t)s + 1];
    }
    float v = __ldg(&g_sa[i]) + __ldg(&g_sb[j]) + __ldg(bfc);
    out[s] = 1.f / (1.f + __expf(-v));
}

// ---------------- launch ----------------
extern "C" void kernel_launch(void* const* d_in, const int* in_sizes, int n_in,
                              void* d_out, int out_size) {
    const float* x   = (const float*)d_in[0];
    const void*  ei  = d_in[1];
    const void*  smp = d_in[2];
    const float* W1  = (const float*)d_in[3];
    const float* b1  = (const float*)d_in[4];
    const float* W2  = (const float*)d_in[5];
    const float* b2  = (const float*)d_in[6];
    const float* W3  = (const float*)d_in[7];
    const float* b3  = (const float*)d_in[8];
    const float* Wfc = (const float*)d_in[9];
    const float* bfc = (const float*)d_in[10];
    float* out = (float*)d_out;

    const int nb_scan = (N_NODES + 1023) / 1024;   // 98

    k_init<<<(N_NODES + 255) / 256, 256>>>((const int*)ei, (const int*)smp);
    k_count<<<(E_EDGES + 255) / 256, 256>>>(ei);
    k_scanA<<<nb_scan, 256>>>();
    k_scanB<<<1, 128>>>(nb_scan);
    k_scanC<<<(N_NODES + 255) / 256, 256>>>(b3, Wfc);
    k_place<<<(E_EDGES + 255) / 256, 256>>>();
    k_mm1<<<(N_NODES + 127) / 128, 128>>>(x, W1);
    k_layer1<<<(N_NODES + 7) / 8, 256>>>(b1, W2);
    k_layer2<<<(N_NODES + 7) / 8, 256>>>(b2, W3, Wfc);
    k_layer3<<<(N_NODES + 7) / 8, 256>>>();
    k_final<<<(S_SAMP + 255) / 256, 256>>>(smp, bfc, out);
}

// round 3
// speedup vs baseline: 1.3296x; 1.1488x over previous
#include <cuda_runtime.h>
#include <math.h>

#define N_NODES 100000
#define E_EDGES 3200000
#define S_SAMP  1000000
#define FULLM   0xffffffffu

// ---------------- device scratch (static: no allocations allowed) ----------------
__device__ __align__(16) int   g_cnt[N_NODES];
__device__ __align__(16) int   g_off[N_NODES];
__device__ int   g_bsum[128];
__device__ int   g_tsrc[E_EDGES];
__device__ int   g_tdst[E_EDGES];
__device__ int   g_esrc[E_EDGES];         // src sorted by dst (CSR payload)
__device__ float g_dinv[N_NODES];
__device__ __align__(16) float g_y1[N_NODES * 8];
__device__ __align__(16) float g_y2[N_NODES * 16];
__device__ __align__(8)  float2 g_z[N_NODES];    // (y3 . Wa, y3 . Wb)
__device__ float g_sa[N_NODES];
__device__ float g_sb[N_NODES];
__device__ float2 g_cab;                  // (b3 . Wa, b3 . Wb)
__device__ int g_flags[2];                // [0]: edge_index is int32, [1]: samples is int32

// ---------------- packed f32x2 helpers ----------------
__device__ __forceinline__ unsigned long long pack2(float a, float b) {
    unsigned long long r;
    asm("mov.b64 %0, {%1, %2};" : "=l"(r) : "f"(a), "f"(b));
    return r;
}
__device__ __forceinline__ float2 unpack2(unsigned long long v) {
    float2 f;
    asm("mov.b64 {%0, %1}, %2;" : "=f"(f.x), "=f"(f.y) : "l"(v));
    return f;
}
__device__ __forceinline__ void fma2(unsigned long long& d, unsigned long long a, unsigned long long b) {
    asm("fma.rn.f32x2 %0, %1, %2, %3;" : "=l"(d) : "l"(a), "l"(b), "l"(d));
}

// ---------------- init: zero counts + dtype detection + head constants ----------------
__global__ void k_init(const int* __restrict__ ei, const int* __restrict__ sm,
                       const float* __restrict__ b3, const float* __restrict__ Wfc) {
    int i = blockIdx.x * blockDim.x + threadIdx.x;
    if (i < N_NODES) g_cnt[i] = 0;
    if (blockIdx.x == 0) {
        if (threadIdx.x == 0) {
            g_flags[0] = 0; g_flags[1] = 0;
            float ca = 0.f, cb = 0.f;
            #pragma unroll
            for (int f = 0; f < 32; f++) { ca += b3[f] * Wfc[f]; cb += b3[f] * Wfc[32 + f]; }
            g_cab = make_float2(ca, cb);
        }
        __syncthreads();
        int e_nz = 0, s_nz = 0;
        for (int k = threadIdx.x; k < 1024; k += 256) {
            if (ei[2 * k + 1] != 0) e_nz = 1;
            if (sm[2 * k + 1] != 0) s_nz = 1;
        }
        if (e_nz) atomicOr(&g_flags[0], 1);
        if (s_nz) atomicOr(&g_flags[1], 1);
    }
}

// ---------------- edge preprocessing: count + stash as int32 ----------------
__global__ void k_count(const void* __restrict__ eip) {
    int e = blockIdx.x * blockDim.x + threadIdx.x;
    if (e >= E_EDGES) return;
    int s, d;
    if (g_flags[0]) {
        const int* p = (const int*)eip;
        s = p[e]; d = p[E_EDGES + e];
    } else {
        const long long* p = (const long long*)eip;
        s = (int)p[e]; d = (int)p[(size_t)E_EDGES + e];
    }
    g_tsrc[e] = s; g_tdst[e] = d;
    atomicAdd(&g_cnt[d], 1);
}

__global__ void k_dinv() {
    int i = blockIdx.x * blockDim.x + threadIdx.x;
    if (i < N_NODES) g_dinv[i] = rsqrtf((float)g_cnt[i] + 1.0f);
}

// ---------------- y1 = dinv * (x @ W1), 100000x512 @ 512x8, packed f32x2 FMA ----------------
// 128 threads, 512 nodes/block, 4 nodes/thread (cols t, t+128, t+256, t+384).
// x staged transposed sx[k][node] (conflict-free), double-buffered.
// Weights read via uniform LDG (L1-resident, broadcast).
#define MM_M 512
#define MM_NB ((N_NODES + MM_M - 1) / MM_M)    // 196
__global__ void __launch_bounds__(128) k_mm1(const float* __restrict__ x,
                                             const float* __restrict__ W1) {
    __shared__ float sx[2][8][MM_M];           // 32 KB
    const int t = threadIdx.x;
    const int base = blockIdx.x * MM_M;
    const float4* x4 = (const float4*)x;
    const unsigned long long* W2p = (const unsigned long long*)W1;   // row k = 4 packed pairs

    unsigned long long acc[4][4];
    #pragma unroll
    for (int n = 0; n < 4; n++)
        #pragma unroll
        for (int o = 0; o < 4; o++) acc[n][o] = 0ULL;

    // prefetch chunk 0
    float4 pf[8];
    #pragma unroll
    for (int r = 0; r < 8; r++) {
        int L = t + 128 * r, nl = L >> 1, j = L & 1;
        int gn = base + nl; if (gn > N_NODES - 1) gn = N_NODES - 1;
        pf[r] = x4[(size_t)gn * 128 + j];
    }
    #pragma unroll
    for (int r = 0; r < 8; r++) {
        int L = t + 128 * r, nl = L >> 1, kk0 = (L & 1) * 4;
        sx[0][kk0 + 0][nl] = pf[r].x;
        sx[0][kk0 + 1][nl] = pf[r].y;
        sx[0][kk0 + 2][nl] = pf[r].z;
        sx[0][kk0 + 3][nl] = pf[r].w;
    }
    __syncthreads();

    int p = 0;
    for (int c = 0; c < 64; c++) {
        // prefetch chunk c+1
        if (c + 1 < 64) {
            #pragma unroll
            for (int r = 0; r < 8; r++) {
                int L = t + 128 * r, nl = L >> 1, j = L & 1;
                int gn = base + nl; if (gn > N_NODES - 1) gn = N_NODES - 1;
                pf[r] = x4[(size_t)gn * 128 + (c + 1) * 2 + j];
            }
        }
        // compute chunk c from sx[p]
        #pragma unroll
        for (int kk = 0; kk < 8; kk++) {
            int k = c * 8 + kk;
            unsigned long long w0 = __ldg(&W2p[k * 4 + 0]);
            unsigned long long w1 = __ldg(&W2p[k * 4 + 1]);
            unsigned long long w2 = __ldg(&W2p[k * 4 + 2]);
            unsigned long long w3 = __ldg(&W2p[k * 4 + 3]);
            #pragma unroll
            for (int n = 0; n < 4; n++) {
                float xv = sx[p][kk][t + 128 * n];
                unsigned long long xx = pack2(xv, xv);
                fma2(acc[n][0], xx, w0);
                fma2(acc[n][1], xx, w1);
                fma2(acc[n][2], xx, w2);
                fma2(acc[n][3], xx, w3);
            }
        }
        // stage chunk c+1 into the other buffer
        if (c + 1 < 64) {
            #pragma unroll
            for (int r = 0; r < 8; r++) {
                int L = t + 128 * r, nl = L >> 1, kk0 = (L & 1) * 4;
                sx[1 - p][kk0 + 0][nl] = pf[r].x;
                sx[1 - p][kk0 + 1][nl] = pf[r].y;
                sx[1 - p][kk0 + 2][nl] = pf[r].z;
                sx[1 - p][kk0 + 3][nl] = pf[r].w;
            }
        }
        __syncthreads();
        p ^= 1;
    }

    float4* y14 = (float4*)g_y1;
    #pragma unroll
    for (int n = 0; n < 4; n++) {
        int gn = base + t + 128 * n;
        if (gn < N_NODES) {
            float di = g_dinv[gn];
            float2 p0 = unpack2(acc[n][0]), p1 = unpack2(acc[n][1]);
            float2 p2 = unpack2(acc[n][2]), p3 = unpack2(acc[n][3]);
            y14[gn * 2 + 0] = make_float4(p0.x * di, p0.y * di, p1.x * di, p1.y * di);
            y14[gn * 2 + 1] = make_float4(p2.x * di, p2.y * di, p3.x * di, p3.y * di);
        }
    }
}

// ---------------- scan: 1024 elems / 256-thread block, shuffle based ----------------
__global__ void __launch_bounds__(256) k_scanA() {
    __shared__ int ws[8];
    __shared__ int wtot;
    int t = threadIdx.x, lane = t & 31, warp = t >> 5;
    int base = blockIdx.x * 1024 + t * 4;
    int4 v = make_int4(0, 0, 0, 0);
    if (base + 3 < N_NODES) v = *(const int4*)&g_cnt[base];
    else {
        if (base + 0 < N_NODES) v.x = g_cnt[base + 0];
        if (base + 1 < N_NODES) v.y = g_cnt[base + 1];
        if (base + 2 < N_NODES) v.z = g_cnt[base + 2];
    }
    int tsum = v.x + v.y + v.z + v.w;
    int inc = tsum;
    #pragma unroll
    for (int o = 1; o < 32; o <<= 1) {
        int u = __shfl_up_sync(FULLM, inc, o);
        if (lane >= o) inc += u;
    }
    if (lane == 31) ws[warp] = inc;
    __syncthreads();
    if (warp == 0) {
        int w = (lane < 8) ? ws[lane] : 0;
        int wi = w;
        #pragma unroll
        for (int o = 1; o < 8; o <<= 1) {
            int u = __shfl_up_sync(FULLM, wi, o);
            if (lane >= o) wi += u;
        }
        if (lane < 8) ws[lane] = wi - w;      // exclusive warp base
        if (lane == 7) wtot = wi;             // block total
    }
    __syncthreads();
    int b = ws[warp] + inc - tsum;            // exclusive thread base
    int4 o;
    o.x = b + v.x; o.y = o.x + v.y; o.z = o.y + v.z; o.w = o.z + v.w;
    if (base + 3 < N_NODES) *(int4*)&g_off[base] = o;   // inclusive (fixed in scanC)
    else {
        if (base + 0 < N_NODES) g_off[base + 0] = o.x;
        if (base + 1 < N_NODES) g_off[base + 1] = o.y;
        if (base + 2 < N_NODES) g_off[base + 2] = o.z;
    }
    if (t == 0) g_bsum[blockIdx.x] = wtot;
}

// inclusive -> global exclusive; each block redundantly sums its block-prefix (<=98 values)
__global__ void __launch_bounds__(256) k_scanC() {
    int nb = blockIdx.x;                      // same 1024-range as scanA block nb
    int bbase = 0;
    for (int i = 0; i < nb; i++) bbase += g_bsum[i];
    int base = nb * 1024 + threadIdx.x * 4;
    if (base + 3 < N_NODES) {
        int4 o = *(const int4*)&g_off[base];
        int4 c = *(const int4*)&g_cnt[base];
        o.x += bbase - c.x; o.y += bbase - c.y; o.z += bbase - c.z; o.w += bbase - c.w;
        *(int4*)&g_off[base] = o;
    } else {
        for (int q = 0; q < 4; q++)
            if (base + q < N_NODES) g_off[base + q] += bbase - g_cnt[base + q];
    }
}

// ---------------- counting-sort placement (atomic cursor on g_off) ----------------
// After this kernel g_off[n] == end of bucket n; layers use e0 = g_off[n] - g_cnt[n].
__global__ void k_place() {
    int e = blockIdx.x * blockDim.x + threadIdx.x;
    if (e >= E_EDGES) return;
    int d = g_tdst[e];
    int pos = atomicAdd(&g_off[d], 1);
    g_esrc[pos] = g_tsrc[e];
}

// ---------------- Layer 1: agg(y1) -> relu -> y2 = dinv*(h1@W2) ----------------
__global__ void __launch_bounds__(256) k_layer1(const float* __restrict__ b1,
                                                const float* __restrict__ W2) {
    __shared__ float sW2[128];   // 8x16
    int t = threadIdx.x;
    if (t < 128) sW2[t] = W2[t];
    __syncthreads();
    int warp = t >> 5, lane = t & 31;
    int n = blockIdx.x * 8 + warp;
    if (n >= N_NODES) return;
    int end = g_off[n], cnt = g_cnt[n], e0 = end - cnt;
    int f = lane & 7;
    float acc = 0.f;
    for (int e = (lane >> 3); e < cnt; e += 4) {
        int s = g_esrc[e0 + e];
        acc += __ldg(&g_y1[s * 8 + f]);
    }
    acc += __shfl_down_sync(FULLM, acc, 16);
    acc += __shfl_down_sync(FULLM, acc, 8);
    float di = g_dinv[n];
    float h = 0.f;
    if (lane < 8) h = fmaxf(di * (acc + g_y1[n * 8 + lane]) + b1[lane], 0.f);
    float out = 0.f;
    int j = lane & 15;
    #pragma unroll
    for (int k = 0; k < 8; k++) {
        float hk = __shfl_sync(FULLM, h, k);
        out += hk * sW2[k * 16 + j];
    }
    if (lane < 16) g_y2[n * 16 + lane] = di * out;
}

// ---------------- Layer 2: agg(y2) -> relu -> y3 = dinv*(h2@W3), collapse to z ----------------
__global__ void __launch_bounds__(256) k_layer2(const float* __restrict__ b2,
                                                const float* __restrict__ W3,
                                                const float* __restrict__ Wfc) {
    __shared__ float sW3[512];   // 16x32
    __shared__ float sWfc[64];
    int t = threadIdx.x;
    for (int i = t; i < 512; i += 256) sW3[i] = W3[i];
    if (t < 64) sWfc[t] = Wfc[t];
    __syncthreads();
    int warp = t >> 5, lane = t & 31;
    int n = blockIdx.x * 8 + warp;
    if (n >= N_NODES) return;
    int end = g_off[n], cnt = g_cnt[n], e0 = end - cnt;
    int f = lane & 15;
    float acc = 0.f;
    for (int e = (lane >> 4); e < cnt; e += 2) {
        int s = g_esrc[e0 + e];
        acc += __ldg(&g_y2[s * 16 + f]);
    }
    acc += __shfl_down_sync(FULLM, acc, 16);
    float di = g_dinv[n];
    float h = 0.f;
    if (lane < 16) h = fmaxf(di * (acc + g_y2[n * 16 + lane]) + b2[lane], 0.f);
    float out = 0.f;
    #pragma unroll
    for (int k = 0; k < 16; k++) {
        float hk = __shfl_sync(FULLM, h, k);
        out += hk * sW3[k * 32 + lane];
    }
    float y3v = di * out;                       // y3[n][lane]
    float za = y3v * sWfc[lane];
    float zb = y3v * sWfc[32 + lane];
    #pragma unroll
    for (int o = 16; o; o >>= 1) {
        za += __shfl_xor_sync(FULLM, za, o);
        zb += __shfl_xor_sync(FULLM, zb, o);
    }
    if (lane == 0) g_z[n] = make_float2(za, zb);
}

// ---------------- Layer 3 (scalarized): sa/sb = dinv*(sum z[src] + z[n]) + cab ----------------
__global__ void __launch_bounds__(256) k_layer3() {
    int t = threadIdx.x;
    int warp = t >> 5, lane = t & 31;
    int n = blockIdx.x * 8 + warp;
    if (n >= N_NODES) return;
    int end = g_off[n], cnt = g_cnt[n], e0 = end - cnt;
    float ax = 0.f, ay = 0.f;
    for (int e = lane; e < cnt; e += 32) {
        int s = g_esrc[e0 + e];
        float2 z = __ldg(&g_z[s]);
        ax += z.x; ay += z.y;
    }
    #pragma unroll
    for (int o = 16; o; o >>= 1) {
        ax += __shfl_xor_sync(FULLM, ax, o);
        ay += __shfl_xor_sync(FULLM, ay, o);
    }
    if (lane == 0) {
        float di = g_dinv[n];
        float2 zn = g_z[n];
        g_sa[n] = di * (ax + zn.x) + g_cab.x;
        g_sb[n] = di * (ay + zn.y) + g_cab.y;
    }
}

// ---------------- Final: out[s] = sigmoid(sa[i] + sb[j] + bfc) ----------------
__global__ void __launch_bounds__(256) k_final(const void* __restrict__ smp,
                                               const float* __restrict__ bfc,
                                               float* __restrict__ out) {
    int s = blockIdx.x * 256 + threadIdx.x;
    if (s >= S_SAMP) return;
    long long i, j;
    if (g_flags[1]) {
        const int* p = (const int*)smp;
        i = p[2 * s]; j = p[2 * s + 1];
    } else {
        const long long* p = (const long long*)smp;
        i = p[2 * (size_t)s]; j = p[2 * (size_t)s + 1];
    }
    float v = __ldg(&g_sa[i]) + __ldg(&g_sb[j]) + __ldg(bfc);
    out[s] = 1.f / (1.f + __expf(-v));
}

// ---------------- launch ----------------
extern "C" void kernel_launch(void* const* d_in, const int* in_sizes, int n_in,
                              void* d_out, int out_size) {
    const float* x   = (const float*)d_in[0];
    const void*  ei  = d_in[1];
    const void*  smp = d_in[2];
    const float* W1  = (const float*)d_in[3];
    const float* b1  = (const float*)d_in[4];
    const float* W2  = (const float*)d_in[5];
    const float* b2  = (const float*)d_in[6];
    const float* W3  = (const float*)d_in[7];
    const float* b3  = (const float*)d_in[8];
    const float* Wfc = (const float*)d_in[9];
    const float* bfc = (const float*)d_in[10];
    float* out = (float*)d_out;

    const int nb_scan = (N_NODES + 1023) / 1024;   // 98

    k_init<<<(N_NODES + 255) / 256, 256>>>((const int*)ei, (const int*)smp, b3, Wfc);
    k_count<<<(E_EDGES + 255) / 256, 256>>>(ei);
    k_dinv<<<(N_NODES + 255) / 256, 256>>>();
    k_mm1<<<MM_NB, 128>>>(x, W1);                  // launch #4: profiled slot
    k_scanA<<<nb_scan, 256>>>();
    k_scanC<<<nb_scan, 256>>>();
    k_place<<<(E_EDGES + 255) / 256, 256>>>();
    k_layer1<<<(N_NODES + 7) / 8, 256>>>(b1, W2);
    k_layer2<<<(N_NODES + 7) / 8, 256>>>(b2, W3, Wfc);
    k_layer3<<<(N_NODES + 7) / 8, 256>>>();
    k_final<<<(S_SAMP + 255) / 256, 256>>>(smp, bfc, out);
}

// round 4
// speedup vs baseline: 1.3966x; 1.0504x over previous
#include <cuda_runtime.h>
#include <math.h>

#define N_NODES 100000
#define E_EDGES 3200000
#define S_SAMP  1000000
#define FULLM   0xffffffffu

// ---------------- device scratch (static: no allocations allowed) ----------------
__device__ __align__(16) int   g_cnt[N_NODES];
__device__ __align__(16) int   g_off[N_NODES];
__device__ int   g_bsum[128];
__device__ int   g_tsrc[E_EDGES];
__device__ int   g_tdst[E_EDGES];
__device__ int   g_esrc[E_EDGES];         // src sorted by dst (CSR payload)
__device__ __align__(16) float g_dinv[N_NODES];
__device__ __align__(16) float g_y1[N_NODES * 8];
__device__ __align__(16) float g_y2[N_NODES * 16];
__device__ __align__(8)  float2 g_z[N_NODES];    // (y3 . Wa, y3 . Wb)
__device__ float g_sa[N_NODES];
__device__ float g_sb[N_NODES];
__device__ float2 g_cab;                  // (b3 . Wa, b3 . Wb)
__device__ int g_flags[2];                // [0]: edge_index is int32, [1]: samples is int32

// ---------------- init: zero counts + dtype detection + head constants ----------------
__global__ void k_init(const int* __restrict__ ei, const int* __restrict__ sm,
                       const float* __restrict__ b3, const float* __restrict__ Wfc) {
    int i = blockIdx.x * blockDim.x + threadIdx.x;
    if (i < N_NODES) g_cnt[i] = 0;
    if (blockIdx.x == 0) {
        if (threadIdx.x == 0) {
            g_flags[0] = 0; g_flags[1] = 0;
            float ca = 0.f, cb = 0.f;
            #pragma unroll
            for (int f = 0; f < 32; f++) { ca += b3[f] * Wfc[f]; cb += b3[f] * Wfc[32 + f]; }
            g_cab = make_float2(ca, cb);
        }
        __syncthreads();
        int e_nz = 0, s_nz = 0;
        for (int k = threadIdx.x; k < 1024; k += 256) {
            if (ei[2 * k + 1] != 0) e_nz = 1;
            if (sm[2 * k + 1] != 0) s_nz = 1;
        }
        if (e_nz) atomicOr(&g_flags[0], 1);
        if (s_nz) atomicOr(&g_flags[1], 1);
    }
}

// ---------------- edge preprocessing: count + stash as int32 ----------------
__global__ void k_count(const void* __restrict__ eip) {
    int e = blockIdx.x * blockDim.x + threadIdx.x;
    if (e >= E_EDGES) return;
    int s, d;
    if (g_flags[0]) {
        const int* p = (const int*)eip;
        s = p[e]; d = p[E_EDGES + e];
    } else {
        const long long* p = (const long long*)eip;
        s = (int)p[e]; d = (int)p[(size_t)E_EDGES + e];
    }
    g_tsrc[e] = s; g_tdst[e] = d;
    atomicAdd(&g_cnt[d], 1);
}

// ---------------- scan (+dinv): 1024 elems / 256-thread block, shuffle based ----------------
__global__ void __launch_bounds__(256) k_scanA() {
    __shared__ int ws[8];
    __shared__ int wtot;
    int t = threadIdx.x, lane = t & 31, warp = t >> 5;
    int base = blockIdx.x * 1024 + t * 4;
    int4 v = make_int4(0, 0, 0, 0);
    if (base + 3 < N_NODES) v = *(const int4*)&g_cnt[base];
    else {
        if (base + 0 < N_NODES) v.x = g_cnt[base + 0];
        if (base + 1 < N_NODES) v.y = g_cnt[base + 1];
        if (base + 2 < N_NODES) v.z = g_cnt[base + 2];
    }
    // dinv (degrees are final here)
    if (base + 3 < N_NODES) {
        float4 dv;
        dv.x = rsqrtf((float)v.x + 1.0f);
        dv.y = rsqrtf((float)v.y + 1.0f);
        dv.z = rsqrtf((float)v.z + 1.0f);
        dv.w = rsqrtf((float)v.w + 1.0f);
        *(float4*)&g_dinv[base] = dv;
    } else {
        if (base + 0 < N_NODES) g_dinv[base + 0] = rsqrtf((float)v.x + 1.0f);
        if (base + 1 < N_NODES) g_dinv[base + 1] = rsqrtf((float)v.y + 1.0f);
        if (base + 2 < N_NODES) g_dinv[base + 2] = rsqrtf((float)v.z + 1.0f);
    }
    int tsum = v.x + v.y + v.z + v.w;
    int inc = tsum;
    #pragma unroll
    for (int o = 1; o < 32; o <<= 1) {
        int u = __shfl_up_sync(FULLM, inc, o);
        if (lane >= o) inc += u;
    }
    if (lane == 31) ws[warp] = inc;
    __syncthreads();
    if (warp == 0) {
        int w = (lane < 8) ? ws[lane] : 0;
        int wi = w;
        #pragma unroll
        for (int o = 1; o < 8; o <<= 1) {
            int u = __shfl_up_sync(FULLM, wi, o);
            if (lane >= o) wi += u;
        }
        if (lane < 8) ws[lane] = wi - w;      // exclusive warp base
        if (lane == 7) wtot = wi;             // block total
    }
    __syncthreads();
    int b = ws[warp] + inc - tsum;            // exclusive thread base
    int4 o;
    o.x = b + v.x; o.y = o.x + v.y; o.z = o.y + v.z; o.w = o.z + v.w;
    if (base + 3 < N_NODES) *(int4*)&g_off[base] = o;   // inclusive (fixed in scanC)
    else {
        if (base + 0 < N_NODES) g_off[base + 0] = o.x;
        if (base + 1 < N_NODES) g_off[base + 1] = o.y;
        if (base + 2 < N_NODES) g_off[base + 2] = o.z;
    }
    if (t == 0) g_bsum[blockIdx.x] = wtot;
}

// ---------------- y1 = dinv * (x @ W1): warp-per-node streaming ----------------
// Each warp streams one 2KB x-row (4 x LDG.128/lane, MLP=4), weights transposed
// in smem (LDS.128, conflict-free), butterfly-reduce, lane0 stores 2x STG.128.
__global__ void __launch_bounds__(256) k_mm1(const float* __restrict__ x,
                                             const float* __restrict__ W1) {
    __shared__ float sWt[8][512];     // transposed W1 (16 KB)
    int t = threadIdx.x;
    for (int i = t; i < 4096; i += 256) {
        int k = i >> 3, o = i & 7;    // read W1 coalesced
        sWt[o][k] = W1[i];
    }
    __syncthreads();

    int warp = t >> 5, lane = t & 31;
    int n = blockIdx.x * 8 + warp;
    if (n >= N_NODES) return;

    const float4* x4 = (const float4*)x;
    const float4* sWt4 = (const float4*)sWt;   // sWt4[o*128 + k4]

    float4 xb[4];
    #pragma unroll
    for (int q = 0; q < 4; q++)
        xb[q] = __ldg(&x4[(size_t)n * 128 + lane + 32 * q]);

    float a0 = 0.f, a1 = 0.f, a2 = 0.f, a3 = 0.f, a4 = 0.f, a5 = 0.f, a6 = 0.f, a7 = 0.f;
    #pragma unroll
    for (int q = 0; q < 4; q++) {
        float4 xv = xb[q];
        int k4 = lane + 32 * q;
        #define DOT(o, ac) { float4 wv = sWt4[(o) * 128 + k4]; \
            ac = fmaf(xv.x, wv.x, ac); ac = fmaf(xv.y, wv.y, ac); \
            ac = fmaf(xv.z, wv.z, ac); ac = fmaf(xv.w, wv.w, ac); }
        DOT(0, a0) DOT(1, a1) DOT(2, a2) DOT(3, a3)
        DOT(4, a4) DOT(5, a5) DOT(6, a6) DOT(7, a7)
        #undef DOT
    }
    #pragma unroll
    for (int o = 16; o; o >>= 1) {
        a0 += __shfl_xor_sync(FULLM, a0, o);
        a1 += __shfl_xor_sync(FULLM, a1, o);
        a2 += __shfl_xor_sync(FULLM, a2, o);
        a3 += __shfl_xor_sync(FULLM, a3, o);
        a4 += __shfl_xor_sync(FULLM, a4, o);
        a5 += __shfl_xor_sync(FULLM, a5, o);
        a6 += __shfl_xor_sync(FULLM, a6, o);
        a7 += __shfl_xor_sync(FULLM, a7, o);
    }
    if (lane == 0) {
        float di = g_dinv[n];
        float4* y14 = (float4*)g_y1;
        y14[n * 2 + 0] = make_float4(a0 * di, a1 * di, a2 * di, a3 * di);
        y14[n * 2 + 1] = make_float4(a4 * di, a5 * di, a6 * di, a7 * di);
    }
}

// inclusive -> global exclusive; each block redundantly sums its block-prefix (<=98 values)
__global__ void __launch_bounds__(256) k_scanC() {
    int nb = blockIdx.x;                      // same 1024-range as scanA block nb
    int bbase = 0;
    for (int i = 0; i < nb; i++) bbase += g_bsum[i];
    int base = nb * 1024 + threadIdx.x * 4;
    if (base + 3 < N_NODES) {
        int4 o = *(const int4*)&g_off[base];
        int4 c = *(const int4*)&g_cnt[base];
        o.x += bbase - c.x; o.y += bbase - c.y; o.z += bbase - c.z; o.w += bbase - c.w;
        *(int4*)&g_off[base] = o;
    } else {
        for (int q = 0; q < 4; q++)
            if (base + q < N_NODES) g_off[base + q] += bbase - g_cnt[base + q];
    }
}

// ---------------- counting-sort placement (atomic cursor on g_off) ----------------
// After this kernel g_off[n] == end of bucket n; layers use e0 = g_off[n] - g_cnt[n].
__global__ void k_place() {
    int e = blockIdx.x * blockDim.x + threadIdx.x;
    if (e >= E_EDGES) return;
    int d = g_tdst[e];
    int pos = atomicAdd(&g_off[d], 1);
    g_esrc[pos] = g_tsrc[e];
}

// ---------------- Layer 1: agg(y1) -> relu -> y2 = dinv*(h1@W2) ----------------
__global__ void __launch_bounds__(256) k_layer1(const float* __restrict__ b1,
                                                const float* __restrict__ W2) {
    __shared__ float sW2[128];   // 8x16
    int t = threadIdx.x;
    if (t < 128) sW2[t] = W2[t];
    __syncthreads();
    int warp = t >> 5, lane = t & 31;
    int n = blockIdx.x * 8 + warp;
    if (n >= N_NODES) return;
    int end = g_off[n], cnt = g_cnt[n], e0 = end - cnt;
    int f = lane & 7;
    float acc = 0.f;
    for (int e = (lane >> 3); e < cnt; e += 4) {
        int s = g_esrc[e0 + e];
        acc += __ldg(&g_y1[s * 8 + f]);
    }
    acc += __shfl_down_sync(FULLM, acc, 16);
    acc += __shfl_down_sync(FULLM, acc, 8);
    float di = g_dinv[n];
    float h = 0.f;
    if (lane < 8) h = fmaxf(di * (acc + g_y1[n * 8 + lane]) + b1[lane], 0.f);
    float out = 0.f;
    int j = lane & 15;
    #pragma unroll
    for (int k = 0; k < 8; k++) {
        float hk = __shfl_sync(FULLM, h, k);
        out += hk * sW2[k * 16 + j];
    }
    if (lane < 16) g_y2[n * 16 + lane] = di * out;
}

// ---------------- Layer 2: agg(y2) -> relu -> y3 = dinv*(h2@W3), collapse to z ----------------
__global__ void __launch_bounds__(256) k_layer2(const float* __restrict__ b2,
                                                const float* __restrict__ W3,
                                                const float* __restrict__ Wfc) {
    __shared__ float sW3[512];   // 16x32
    __shared__ float sWfc[64];
    int t = threadIdx.x;
    for (int i = t; i < 512; i += 256) sW3[i] = W3[i];
    if (t < 64) sWfc[t] = Wfc[t];
    __syncthreads();
    int warp = t >> 5, lane = t & 31;
    int n = blockIdx.x * 8 + warp;
    if (n >= N_NODES) return;
    int end = g_off[n], cnt = g_cnt[n], e0 = end - cnt;
    int f = lane & 15;
    float acc = 0.f;
    for (int e = (lane >> 4); e < cnt; e += 2) {
        int s = g_esrc[e0 + e];
        acc += __ldg(&g_y2[s * 16 + f]);
    }
    acc += __shfl_down_sync(FULLM, acc, 16);
    float di = g_dinv[n];
    float h = 0.f;
    if (lane < 16) h = fmaxf(di * (acc + g_y2[n * 16 + lane]) + b2[lane], 0.f);
    float out = 0.f;
    #pragma unroll
    for (int k = 0; k < 16; k++) {
        float hk = __shfl_sync(FULLM, h, k);
        out += hk * sW3[k * 32 + lane];
    }
    float y3v = di * out;                       // y3[n][lane]
    float za = y3v * sWfc[lane];
    float zb = y3v * sWfc[32 + lane];
    #pragma unroll
    for (int o = 16; o; o >>= 1) {
        za += __shfl_xor_sync(FULLM, za, o);
        zb += __shfl_xor_sync(FULLM, zb, o);
    }
    if (lane == 0) g_z[n] = make_float2(za, zb);
}

// ---------------- Layer 3 (scalarized): sa/sb = dinv*(sum z[src] + z[n]) + cab ----------------
__global__ void __launch_bounds__(256) k_layer3() {
    int t = threadIdx.x;
    int warp = t >> 5, lane = t & 31;
    int n = blockIdx.x * 8 + warp;
    if (n >= N_NODES) return;
    int end = g_off[n], cnt = g_cnt[n], e0 = end - cnt;
    float ax = 0.f, ay = 0.f;
    for (int e = lane; e < cnt; e += 32) {
        int s = g_esrc[e0 + e];
        float2 z = __ldg(&g_z[s]);
        ax += z.x; ay += z.y;
    }
    #pragma unroll
    for (int o = 16; o; o >>= 1) {
        ax += __shfl_xor_sync(FULLM, ax, o);
        ay += __shfl_xor_sync(FULLM, ay, o);
    }
    if (lane == 0) {
        float di = g_dinv[n];
        float2 zn = g_z[n];
        g_sa[n] = di * (ax + zn.x) + g_cab.x;
        g_sb[n] = di * (ay + zn.y) + g_cab.y;
    }
}

// ---------------- Final: out[s] = sigmoid(sa[i] + sb[j] + bfc) ----------------
__global__ void __launch_bounds__(256) k_final(const void* __restrict__ smp,
                                               const float* __restrict__ bfc,
                                               float* __restrict__ out) {
    int s = blockIdx.x * 256 + threadIdx.x;
    if (s >= S_SAMP) return;
    long long i, j;
    if (g_flags[1]) {
        const int* p = (const int*)smp;
        i = p[2 * s]; j = p[2 * s + 1];
    } else {
        const long long* p = (const long long*)smp;
        i = p[2 * (size_t)s]; j = p[2 * (size_t)s + 1];
    }
    float v = __ldg(&g_sa[i]) + __ldg(&g_sb[j]) + __ldg(bfc);
    out[s] = 1.f / (1.f + __expf(-v));
}

// ---------------- launch ----------------
extern "C" void kernel_launch(void* const* d_in, const int* in_sizes, int n_in,
                              void* d_out, int out_size) {
    const float* x   = (const float*)d_in[0];
    const void*  ei  = d_in[1];
    const void*  smp = d_in[2];
    const float* W1  = (const float*)d_in[3];
    const float* b1  = (const float*)d_in[4];
    const float* W2  = (const float*)d_in[5];
    const float* b2  = (const float*)d_in[6];
    const float* W3  = (const float*)d_in[7];
    const float* b3  = (const float*)d_in[8];
    const float* Wfc = (const float*)d_in[9];
    const float* bfc = (const float*)d_in[10];
    float* out = (float*)d_out;

    const int nb_scan = (N_NODES + 1023) / 1024;   // 98

    k_init<<<(N_NODES + 255) / 256, 256>>>((const int*)ei, (const int*)smp, b3, Wfc);
    k_count<<<(E_EDGES + 255) / 256, 256>>>(ei);
    k_scanA<<<nb_scan, 256>>>();
    k_mm1<<<(N_NODES + 7) / 8, 256>>>(x, W1);      // launch #4: profiled slot
    k_scanC<<<nb_scan, 256>>>();
    k_place<<<(E_EDGES + 255) / 256, 256>>>();
    k_layer1<<<(N_NODES + 7) / 8, 256>>>(b1, W2);
    k_layer2<<<(N_NODES + 7) / 8, 256>>>(b2, W3, Wfc);
    k_layer3<<<(N_NODES + 7) / 8, 256>>>();
    k_final<<<(S_SAMP + 255) / 256, 256>>>(smp, bfc, out);
}